// round 10
// baseline (speedup 1.0000x reference)
#include <cuda_runtime.h>

#define DDEPTH 8
#define HDIM   4096
#define NT     512
#define NWARP  (NT / 32)    // 16
#define HPT    8            // hidden dims per thread (512*8 = 4096)
#define EPSV   1e-6f

#define DOT4(a,b) ((a).x*(b).x + (a).y*(b).y + (a).z*(b).z + (a).w*(b).w)

// Persistent CTAs (2/SM), online softmax over depth PAIRS (4 barriers/site).
// Full next-pair prefetch (4 LDG.128) issued before the reduce tail; cross-warp
// scan distributed: 1 LDS.128 + 4-round f4 butterfly per thread, no broadcast.
__global__ __launch_bounds__(NT, 2)
void fullattnres_kernel(const float* __restrict__ values,
                        const float* __restrict__ query,
                        const float* __restrict__ weight,
                        float* __restrict__ out,
                        int SB)
{
    __shared__ float4 red[2][NWARP];   // {ss0,ss1,dp0,dp1} per warp, parity buf

    const int tid  = threadIdx.x;
    const int lane = tid & 31;
    const int warp = tid >> 5;
    const int h    = tid * HPT;
    const size_t dstr = (size_t)SB * HDIM;

    int site = blockIdx.x;
    if (site >= SB) return;

    // fused q*w, loaded ONCE per CTA (persistent)
    const float4 q0 = *(const float4*)(query + h);
    const float4 q1 = *(const float4*)(query + h + 4);
    const float4 w0 = *(const float4*)(weight + h);
    const float4 w1 = *(const float4*)(weight + h + 4);
    const float4 qw0 = make_float4(q0.x*w0.x, q0.y*w0.y, q0.z*w0.z, q0.w*w0.w);
    const float4 qw1 = make_float4(q1.x*w1.x, q1.y*w1.y, q1.z*w1.z, q1.w*w1.w);

    const float* p = values + (size_t)site * HDIM + h;

    // preload pair 0 (depths 0,1) of the first site
    float4 a0 = *(const float4*)(p);
    float4 a1 = *(const float4*)(p + 4);
    float4 b0 = *(const float4*)(p + dstr);
    float4 b1 = *(const float4*)(p + dstr + 4);

    int parity = 0;

    for (;;) {
        float  m = -3.402823466e38f;
        float  s = 0.f;
        float4 acc0 = make_float4(0.f, 0.f, 0.f, 0.f);
        float4 acc1 = make_float4(0.f, 0.f, 0.f, 0.f);

        #pragma unroll
        for (int pr = 0; pr < DDEPTH / 2; pr++) {
            // ── prefetch the ENTIRE next pair first: 4 LDG.128 stay in
            //    flight through the whole reduce tail ──
            const float* pn;
            if (pr < DDEPTH / 2 - 1) {
                pn = p + (size_t)(2 * pr + 2) * dstr;
            } else {
                const int nsite = site + gridDim.x;
                pn = values + (size_t)((nsite < SB) ? nsite : site) * HDIM + h;
            }
            float4 na0 = *(const float4*)(pn);
            float4 na1 = *(const float4*)(pn + 4);
            float4 nb0 = *(const float4*)(pn + dstr);
            float4 nb1 = *(const float4*)(pn + dstr + 4);

            // partials for depths 2pr (a) and 2pr+1 (b)
            float ss0 = DOT4(a0, a0) + DOT4(a1, a1);
            float dp0 = DOT4(qw0, a0) + DOT4(qw1, a1);
            float ss1 = DOT4(b0, b0) + DOT4(b1, b1);
            float dp1 = DOT4(qw0, b0) + DOT4(qw1, b1);

            // warp butterfly over the 4 scalars
            #pragma unroll
            for (int off = 16; off > 0; off >>= 1) {
                ss0 += __shfl_xor_sync(0xFFFFFFFFu, ss0, off);
                ss1 += __shfl_xor_sync(0xFFFFFFFFu, ss1, off);
                dp0 += __shfl_xor_sync(0xFFFFFFFFu, dp0, off);
                dp1 += __shfl_xor_sync(0xFFFFFFFFu, dp1, off);
            }
            if (lane == 0)
                red[parity][warp] = make_float4(ss0, ss1, dp0, dp1);
            __syncthreads();

            // ── distributed cross-warp scan: each lane reads ONE warp
            //    partial, 4-round f4 butterfly within each 16-lane half;
            //    every lane ends with the CTA totals (no broadcast) ──
            float4 t = red[parity][lane & 15];
            #pragma unroll
            for (int off = 8; off > 0; off >>= 1) {
                t.x += __shfl_xor_sync(0xFFFFFFFFu, t.x, off);
                t.y += __shfl_xor_sync(0xFFFFFFFFu, t.y, off);
                t.z += __shfl_xor_sync(0xFFFFFFFFu, t.z, off);
                t.w += __shfl_xor_sync(0xFFFFFFFFu, t.w, off);
            }
            parity ^= 1;

            const float l0 = t.z * rsqrtf(t.x * (1.0f / HDIM) + EPSV);
            const float l1 = t.w * rsqrtf(t.y * (1.0f / HDIM) + EPSV);

            // joint online-softmax update for both depths
            const float mn = fmaxf(m, fmaxf(l0, l1));
            const float cs = __expf(m - mn);     // first pair: exp(-inf)=0
            const float e0 = __expf(l0 - mn);
            const float e1 = __expf(l1 - mn);
            s = s * cs + e0 + e1;
            acc0.x = acc0.x * cs + e0 * a0.x + e1 * b0.x;
            acc0.y = acc0.y * cs + e0 * a0.y + e1 * b0.y;
            acc0.z = acc0.z * cs + e0 * a0.z + e1 * b0.z;
            acc0.w = acc0.w * cs + e0 * a0.w + e1 * b0.w;
            acc1.x = acc1.x * cs + e0 * a1.x + e1 * b1.x;
            acc1.y = acc1.y * cs + e0 * a1.y + e1 * b1.y;
            acc1.z = acc1.z * cs + e0 * a1.z + e1 * b1.z;
            acc1.w = acc1.w * cs + e0 * a1.w + e1 * b1.w;
            m = mn;

            a0 = na0;  a1 = na1;  b0 = nb0;  b1 = nb1;
        }

        // finalize + store this site
        const float inv = 1.0f / s;
        const size_t ob = (size_t)site * HDIM + h;
        *(float4*)(out + ob)     = make_float4(acc0.x*inv, acc0.y*inv, acc0.z*inv, acc0.w*inv);
        *(float4*)(out + ob + 4) = make_float4(acc1.x*inv, acc1.y*inv, acc1.z*inv, acc1.w*inv);

        site += gridDim.x;
        if (site >= SB) break;
        p = values + (size_t)site * HDIM + h;
        // a/b already hold the new site's pair 0 (prefetched at pr==3)
    }
}

extern "C" void kernel_launch(void* const* d_in, const int* in_sizes, int n_in,
                              void* d_out, int out_size)
{
    const float* values = (const float*)d_in[0];  // [D,S,B,H]
    const float* query  = (const float*)d_in[1];  // [H]
    const float* weight = (const float*)d_in[2];  // [H]
    float* out = (float*)d_out;                   // [S,B,H]

    const int H  = in_sizes[1];                   // 4096
    const int SB = out_size / H;                  // S*B = 4096

    int sms = 148;
    cudaDeviceGetAttribute(&sms, cudaDevAttrMultiProcessorCount, 0);
    int grid = 2 * sms;                           // persistent: 2 CTAs per SM
    if (grid > SB) grid = SB;

    fullattnres_kernel<<<grid, NT>>>(values, query, weight, out, SB);
}

// round 11
// speedup vs baseline: 1.4394x; 1.4394x over previous
#include <cuda_runtime.h>

#define DDEPTH 8
#define HDIM   4096
#define NT     512
#define NWARP  (NT / 32)    // 16
#define HPT    8            // hidden dims per thread (512*8 = 4096)
#define EPSV   1e-6f

#define DOT4(a,b) ((a).x*(b).x + (a).y*(b).y + (a).z*(b).z + (a).w*(b).w)

// Persistent CTAs (2/SM), online softmax over depth PAIRS (4 barriers/site).
// R8 skeleton (split prefetch: depth-A before butterfly, depth-B after the
// barrier — keeps live range at the 64-reg cap) + distributed cross-warp scan.
__global__ __launch_bounds__(NT, 2)
void fullattnres_kernel(const float* __restrict__ values,
                        const float* __restrict__ query,
                        const float* __restrict__ weight,
                        float* __restrict__ out,
                        int SB)
{
    __shared__ float4 red[2][NWARP];   // {ss0,ss1,dp0,dp1} per warp, parity buf

    const int tid  = threadIdx.x;
    const int lane = tid & 31;
    const int warp = tid >> 5;
    const int h    = tid * HPT;
    const size_t dstr = (size_t)SB * HDIM;

    int site = blockIdx.x;
    if (site >= SB) return;

    // fused q*w, loaded ONCE per CTA (persistent)
    const float4 q0 = *(const float4*)(query + h);
    const float4 q1 = *(const float4*)(query + h + 4);
    const float4 w0 = *(const float4*)(weight + h);
    const float4 w1 = *(const float4*)(weight + h + 4);
    const float4 qw0 = make_float4(q0.x*w0.x, q0.y*w0.y, q0.z*w0.z, q0.w*w0.w);
    const float4 qw1 = make_float4(q1.x*w1.x, q1.y*w1.y, q1.z*w1.z, q1.w*w1.w);

    const float* p = values + (size_t)site * HDIM + h;

    // preload pair 0 (depths 0,1) of the first site
    float4 a0 = *(const float4*)(p);
    float4 a1 = *(const float4*)(p + 4);
    float4 b0 = *(const float4*)(p + dstr);
    float4 b1 = *(const float4*)(p + dstr + 4);

    int parity = 0;

    for (;;) {
        float  m = -3.402823466e38f;
        float  s = 0.f;
        float4 acc0 = make_float4(0.f, 0.f, 0.f, 0.f);
        float4 acc1 = make_float4(0.f, 0.f, 0.f, 0.f);

        #pragma unroll
        for (int pr = 0; pr < DDEPTH / 2; pr++) {
            // partials for depths 2pr (a) and 2pr+1 (b)
            float ss0 = DOT4(a0, a0) + DOT4(a1, a1);
            float dp0 = DOT4(qw0, a0) + DOT4(qw1, a1);
            float ss1 = DOT4(b0, b0) + DOT4(b1, b1);
            float dp1 = DOT4(qw0, b0) + DOT4(qw1, b1);

            // prefetch depth-A of the next pair (or next site's depth 0)
            float4 na0, na1, nb0, nb1;
            const float* pn;
            if (pr < DDEPTH / 2 - 1) {
                pn = p + (size_t)(2 * pr + 2) * dstr;
            } else {
                const int nsite = site + gridDim.x;
                pn = values + (size_t)((nsite < SB) ? nsite : site) * HDIM + h;
            }
            na0 = *(const float4*)(pn);
            na1 = *(const float4*)(pn + 4);

            // warp butterfly over the 4 scalars (in flight with the prefetch)
            #pragma unroll
            for (int off = 16; off > 0; off >>= 1) {
                ss0 += __shfl_xor_sync(0xFFFFFFFFu, ss0, off);
                ss1 += __shfl_xor_sync(0xFFFFFFFFu, ss1, off);
                dp0 += __shfl_xor_sync(0xFFFFFFFFu, dp0, off);
                dp1 += __shfl_xor_sync(0xFFFFFFFFu, dp1, off);
            }
            if (lane == 0)
                red[parity][warp] = make_float4(ss0, ss1, dp0, dp1);
            __syncthreads();

            // prefetch depth-B of the next pair (overlaps scan + softmax math)
            nb0 = *(const float4*)(pn + dstr);
            nb1 = *(const float4*)(pn + dstr + 4);

            // distributed cross-warp scan: each lane reads ONE warp partial,
            // 4-round f4 butterfly (offsets <=8 keep it within 16-groups);
            // every lane ends with the CTA totals.
            float4 t = red[parity][lane & 15];
            #pragma unroll
            for (int off = 8; off > 0; off >>= 1) {
                t.x += __shfl_xor_sync(0xFFFFFFFFu, t.x, off);
                t.y += __shfl_xor_sync(0xFFFFFFFFu, t.y, off);
                t.z += __shfl_xor_sync(0xFFFFFFFFu, t.z, off);
                t.w += __shfl_xor_sync(0xFFFFFFFFu, t.w, off);
            }
            parity ^= 1;

            const float l0 = t.z * rsqrtf(t.x * (1.0f / HDIM) + EPSV);
            const float l1 = t.w * rsqrtf(t.y * (1.0f / HDIM) + EPSV);

            // joint online-softmax update for both depths
            const float mn = fmaxf(m, fmaxf(l0, l1));
            const float cs = __expf(m - mn);     // first pair: exp(-inf)=0
            const float e0 = __expf(l0 - mn);
            const float e1 = __expf(l1 - mn);
            s = s * cs + e0 + e1;
            acc0.x = acc0.x * cs + e0 * a0.x + e1 * b0.x;
            acc0.y = acc0.y * cs + e0 * a0.y + e1 * b0.y;
            acc0.z = acc0.z * cs + e0 * a0.z + e1 * b0.z;
            acc0.w = acc0.w * cs + e0 * a0.w + e1 * b0.w;
            acc1.x = acc1.x * cs + e0 * a1.x + e1 * b1.x;
            acc1.y = acc1.y * cs + e0 * a1.y + e1 * b1.y;
            acc1.z = acc1.z * cs + e0 * a1.z + e1 * b1.z;
            acc1.w = acc1.w * cs + e0 * a1.w + e1 * b1.w;
            m = mn;

            a0 = na0;  a1 = na1;  b0 = nb0;  b1 = nb1;
        }

        // finalize + store this site
        const float inv = 1.0f / s;
        const size_t ob = (size_t)site * HDIM + h;
        *(float4*)(out + ob)     = make_float4(acc0.x*inv, acc0.y*inv, acc0.z*inv, acc0.w*inv);
        *(float4*)(out + ob + 4) = make_float4(acc1.x*inv, acc1.y*inv, acc1.z*inv, acc1.w*inv);

        site += gridDim.x;
        if (site >= SB) break;
        p = values + (size_t)site * HDIM + h;
        // a/b already hold the new site's pair 0 (prefetched at pr==3)
    }
}

extern "C" void kernel_launch(void* const* d_in, const int* in_sizes, int n_in,
                              void* d_out, int out_size)
{
    const float* values = (const float*)d_in[0];  // [D,S,B,H]
    const float* query  = (const float*)d_in[1];  // [H]
    const float* weight = (const float*)d_in[2];  // [H]
    float* out = (float*)d_out;                   // [S,B,H]

    const int H  = in_sizes[1];                   // 4096
    const int SB = out_size / H;                  // S*B = 4096

    int sms = 148;
    cudaDeviceGetAttribute(&sms, cudaDevAttrMultiProcessorCount, 0);
    int grid = 2 * sms;                           // persistent: 2 CTAs per SM
    if (grid > SB) grid = SB;

    fullattnres_kernel<<<grid, NT>>>(values, query, weight, out, SB);
}